// round 3
// baseline (speedup 1.0000x reference)
#include <cuda_runtime.h>

#define NN 100000
#define NE 3200000
#define NG 1000

// ---------------- scratch (device globals; no allocation allowed) ----------------
__device__ float g_q[NN * 32];
__device__ float g_k[NN * 32];
__device__ float g_v[NN * 32];
__device__ float g_skip[NN * 32];
__device__ float g_h[NN * 16];     // layer-1 output
__device__ float g_agg[NN * 32];
__device__ float g_denom[NN];
__device__ float g_sums[NG * 32];
__device__ float g_cnt[NG];

// ---------------- reduction helpers (no-return global reds) ----------------
__device__ __forceinline__ void red_add(float* p, float v) {
    asm volatile("red.global.add.f32 [%0], %1;" :: "l"(p), "f"(v) : "memory");
}
__device__ __forceinline__ void red_add4(float* p, float a, float b, float c, float d) {
    asm volatile("red.global.add.v4.f32 [%0], {%1,%2,%3,%4};"
                 :: "l"(p), "f"(a), "f"(b), "f"(c), "f"(d) : "memory");
}

// ---------------- zero kernels ----------------
__global__ void zero_l1() {
    int i = blockIdx.x * blockDim.x + threadIdx.x;
    if (i < NN * 16) g_agg[i] = 0.f;
    if (i < NN) g_denom[i] = 0.f;
}
__global__ void zero_l2() {
    int i = blockIdx.x * blockDim.x + threadIdx.x;
    if (i < NN * 32) g_agg[i] = 0.f;
    if (i < NN) g_denom[i] = 0.f;
}
__global__ void zero_pool() {
    int i = blockIdx.x * blockDim.x + threadIdx.x;
    if (i < NG * 32) g_sums[i] = 0.f;
    if (i < NG) g_cnt[i] = 0.f;
}

// ---------------- node linear, layer 1: x[N,11] -> q,k,v,skip [N,16] ----------------
__global__ void lin1(const float* __restrict__ x,
                     const float* __restrict__ Wq, const float* __restrict__ bq,
                     const float* __restrict__ Wk, const float* __restrict__ bk,
                     const float* __restrict__ Wv, const float* __restrict__ bv,
                     const float* __restrict__ Ws, const float* __restrict__ bs) {
    __shared__ float sW[4][11 * 16];
    __shared__ float sB[4][16];
    {
        const float* Wp[4] = {Wq, Wk, Wv, Ws};
        const float* Bp[4] = {bq, bk, bv, bs};
        for (int t = threadIdx.x; t < 4 * 176; t += blockDim.x)
            sW[t / 176][t % 176] = Wp[t / 176][t % 176];
        for (int t = threadIdx.x; t < 4 * 16; t += blockDim.x)
            sB[t / 16][t % 16] = Bp[t / 16][t % 16];
    }
    __syncthreads();
    int n = blockIdx.x * blockDim.x + threadIdx.x;
    if (n >= NN) return;
    float xv[11];
#pragma unroll
    for (int i = 0; i < 11; i++) xv[i] = x[n * 11 + i];
    float* outp[4] = {g_q, g_k, g_v, g_skip};
#pragma unroll
    for (int m = 0; m < 4; m++) {
#pragma unroll
        for (int j = 0; j < 16; j++) {
            float acc = sB[m][j];
#pragma unroll
            for (int i = 0; i < 11; i++) acc += xv[i] * sW[m][i * 16 + j];
            outp[m][n * 16 + j] = acc;
        }
    }
}

// ---------------- node linear, layer 2: h[N,16] -> q,k,v,skip [N,32] ----------------
__global__ void lin2(const float* __restrict__ Wq, const float* __restrict__ bq,
                     const float* __restrict__ Wk, const float* __restrict__ bk,
                     const float* __restrict__ Wv, const float* __restrict__ bv,
                     const float* __restrict__ Ws, const float* __restrict__ bs) {
    __shared__ float sW[4][16 * 32];
    __shared__ float sB[4][32];
    {
        const float* Wp[4] = {Wq, Wk, Wv, Ws};
        const float* Bp[4] = {bq, bk, bv, bs};
        for (int t = threadIdx.x; t < 4 * 512; t += blockDim.x)
            sW[t / 512][t % 512] = Wp[t / 512][t % 512];
        for (int t = threadIdx.x; t < 4 * 32; t += blockDim.x)
            sB[t / 32][t % 32] = Bp[t / 32][t % 32];
    }
    __syncthreads();
    int n = blockIdx.x * blockDim.x + threadIdx.x;
    if (n >= NN) return;
    float xv[16];
#pragma unroll
    for (int i = 0; i < 16; i++) xv[i] = g_h[n * 16 + i];
    float* outp[4] = {g_q, g_k, g_v, g_skip};
#pragma unroll
    for (int m = 0; m < 4; m++) {
#pragma unroll
        for (int j = 0; j < 32; j++) {
            float acc = sB[m][j];
#pragma unroll
            for (int i = 0; i < 16; i++) acc += xv[i] * sW[m][i * 32 + j];
            outp[m][n * 32 + j] = acc;
        }
    }
}

// ---------------- edge pass, layer 1 (d=16): half-warp per edge ----------------
__global__ void edge16(const int* __restrict__ src, const int* __restrict__ dst) {
    int w = (blockIdx.x * blockDim.x + threadIdx.x) >> 5;   // warp id = edge pair
    int lane = threadIdx.x & 31;
    int half = lane >> 4;
    int l = lane & 15;
    long long e = (long long)w * 2 + half;
    bool valid = e < NE;
    long long ei = valid ? e : 0;
    int s = src[ei];
    int d = dst[ei];
    float qk = g_q[d * 16 + l] * g_k[s * 16 + l];
    qk += __shfl_xor_sync(0xFFFFFFFFu, qk, 8);
    qk += __shfl_xor_sync(0xFFFFFFFFu, qk, 4);
    qk += __shfl_xor_sync(0xFFFFFFFFu, qk, 2);
    qk += __shfl_xor_sync(0xFFFFFFFFu, qk, 1);
    float ev = __expf(qk * 0.25f);   // 1/sqrt(16)
    if (valid) {
        if (l == 0) red_add(&g_denom[d], ev);
        if (l < 4) {
            float4 vv = *(const float4*)&g_v[s * 16 + l * 4];
            red_add4(&g_agg[d * 16 + l * 4], ev * vv.x, ev * vv.y, ev * vv.z, ev * vv.w);
        }
    }
}

// ---------------- edge pass, layer 2 (d=32): warp per edge ----------------
__global__ void edge32(const int* __restrict__ src, const int* __restrict__ dst) {
    int w = (blockIdx.x * blockDim.x + threadIdx.x) >> 5;
    if (w >= NE) return;
    int lane = threadIdx.x & 31;
    int s = src[w];
    int d = dst[w];
    float qk = g_q[d * 32 + lane] * g_k[s * 32 + lane];
    qk += __shfl_xor_sync(0xFFFFFFFFu, qk, 16);
    qk += __shfl_xor_sync(0xFFFFFFFFu, qk, 8);
    qk += __shfl_xor_sync(0xFFFFFFFFu, qk, 4);
    qk += __shfl_xor_sync(0xFFFFFFFFu, qk, 2);
    qk += __shfl_xor_sync(0xFFFFFFFFu, qk, 1);
    float ev = __expf(qk * 0.1767766953f);   // 1/sqrt(32)
    if (lane == 0) red_add(&g_denom[d], ev);
    if (lane < 8) {
        float4 vv = *(const float4*)&g_v[s * 32 + lane * 4];
        red_add4(&g_agg[d * 32 + lane * 4], ev * vv.x, ev * vv.y, ev * vv.z, ev * vv.w);
    }
}

// ---------------- finish layer 1: h = relu(agg/denom + skip) ----------------
__global__ void finish1() {
    int i = blockIdx.x * blockDim.x + threadIdx.x;
    if (i >= NN * 16) return;
    float den = fmaxf(g_denom[i >> 4], 1e-16f);
    g_h[i] = fmaxf(__fdividef(g_agg[i], den) + g_skip[i], 0.f);
}

// ---------------- finish layer 2 + mean-pool accumulate ----------------
// warp per 8 consecutive nodes (batch is sorted -> warp-local aggregation)
__global__ void finish2(const int* __restrict__ batch) {
    int w = (blockIdx.x * blockDim.x + threadIdx.x) >> 5;
    int lane = threadIdx.x & 31;
    int n0 = w * 8;
    if (n0 >= NN) return;
    int nend = n0 + 8;
    if (nend > NN) nend = NN;
    int curg = batch[n0];
    float accum = 0.f, cacc = 0.f;
    for (int n = n0; n < nend; n++) {
        int g = batch[n];
        if (g != curg) {
            red_add(&g_sums[curg * 32 + lane], accum);
            if (lane == 0) red_add(&g_cnt[curg], cacc);
            accum = 0.f; cacc = 0.f; curg = g;
        }
        float den = fmaxf(g_denom[n], 1e-16f);
        accum += fmaxf(__fdividef(g_agg[n * 32 + lane], den) + g_skip[n * 32 + lane], 0.f);
        cacc += 1.f;
    }
    red_add(&g_sums[curg * 32 + lane], accum);
    if (lane == 0) red_add(&g_cnt[curg], cacc);
}

// ---------------- final MLP: g[1000,32] -> 64 relu -> 1 ----------------
__global__ void final_mlp(const float* __restrict__ Wf1, const float* __restrict__ bf1,
                          const float* __restrict__ Wf2, const float* __restrict__ bf2,
                          float* __restrict__ out) {
    __shared__ float sW1[32 * 64];
    __shared__ float sB1[64];
    __shared__ float sW2[64];
    __shared__ float sB2;
    for (int t = threadIdx.x; t < 32 * 64; t += blockDim.x) sW1[t] = Wf1[t];
    for (int t = threadIdx.x; t < 64; t += blockDim.x) { sB1[t] = bf1[t]; sW2[t] = Wf2[t]; }
    if (threadIdx.x == 0) sB2 = bf2[0];
    __syncthreads();
    int g = blockIdx.x * blockDim.x + threadIdx.x;
    if (g >= NG) return;
    float cnt = fmaxf(g_cnt[g], 1.f);
    float gin[32];
#pragma unroll
    for (int i = 0; i < 32; i++) gin[i] = g_sums[g * 32 + i] / cnt;
    float acc2 = sB2;
#pragma unroll
    for (int j = 0; j < 64; j++) {
        float a = sB1[j];
#pragma unroll
        for (int i = 0; i < 32; i++) a += gin[i] * sW1[i * 64 + j];
        acc2 += fmaxf(a, 0.f) * sW2[j];
    }
    out[g] = acc2;
}

// ---------------- host launch ----------------
extern "C" void kernel_launch(void* const* d_in, const int* in_sizes, int n_in,
                              void* d_out, int out_size) {
    const float* x = (const float*)d_in[0];
    const int* eidx = (const int*)d_in[1];   // JAX x64 disabled -> int32
    const int* src = eidx;
    const int* dst = eidx + NE;
    const int* batch = (const int*)d_in[2];
    const float *Wq1 = (const float*)d_in[3], *bq1 = (const float*)d_in[4];
    const float *Wk1 = (const float*)d_in[5], *bk1 = (const float*)d_in[6];
    const float *Wv1 = (const float*)d_in[7], *bv1 = (const float*)d_in[8];
    const float *Ws1 = (const float*)d_in[9], *bs1 = (const float*)d_in[10];
    const float *Wq2 = (const float*)d_in[11], *bq2 = (const float*)d_in[12];
    const float *Wk2 = (const float*)d_in[13], *bk2 = (const float*)d_in[14];
    const float *Wv2 = (const float*)d_in[15], *bv2 = (const float*)d_in[16];
    const float *Ws2 = (const float*)d_in[17], *bs2 = (const float*)d_in[18];
    const float *Wf1 = (const float*)d_in[19], *bf1 = (const float*)d_in[20];
    const float *Wf2 = (const float*)d_in[21], *bf2 = (const float*)d_in[22];
    float* out = (float*)d_out;

    // ---- layer 1 ----
    zero_l1<<<(NN * 16 + 255) / 256, 256>>>();
    lin1<<<(NN + 127) / 128, 128>>>(x, Wq1, bq1, Wk1, bk1, Wv1, bv1, Ws1, bs1);
    {
        long long warps = (NE + 1) / 2;            // half-warp per edge
        long long threads = warps * 32;
        edge16<<<(unsigned)((threads + 255) / 256), 256>>>(src, dst);
    }
    finish1<<<(NN * 16 + 255) / 256, 256>>>();

    // ---- layer 2 ----
    zero_l2<<<(NN * 32 + 255) / 256, 256>>>();
    lin2<<<(NN + 127) / 128, 128>>>(Wq2, bq2, Wk2, bk2, Wv2, bv2, Ws2, bs2);
    {
        long long threads = (long long)NE * 32;    // warp per edge
        edge32<<<(unsigned)((threads + 255) / 256), 256>>>(src, dst);
    }

    // ---- pool + head ----
    zero_pool<<<(NG * 32 + 255) / 256, 256>>>();
    {
        long long warps = (NN + 7) / 8;
        long long threads = warps * 32;
        finish2<<<(unsigned)((threads + 255) / 256), 256>>>(batch);
    }
    final_mlp<<<(NG + 255) / 256, 256>>>(Wf1, bf1, Wf2, bf2, out);
}

// round 4
// speedup vs baseline: 2.0205x; 2.0205x over previous
#include <cuda_runtime.h>

#define NN 100000
#define NE 3200000
#define NG 1000
#define NBLK ((NN + 255) / 256)   // 391

// ---------------- scratch (device globals; no allocation allowed) ----------------
__device__ int   g_deg[NN];        // in-degree per dst node
__device__ int   g_row[NN];        // CSR row offsets (exclusive scan of deg)
__device__ int   g_cur[NN];        // scatter cursors
__device__ int   g_part[512];      // block partial sums for scan
__device__ int   g_ssrc[NE];       // src ids sorted by dst
__device__ float g_q[NN * 32];
__device__ float g_kv[NN * 64];    // interleaved k|v per node (layer1: stride 32, layer2: stride 64)
__device__ float g_skip[NN * 32];
__device__ float g_h[NN * 16];     // layer-1 output
__device__ float g_sums[NG * 32];
__device__ float g_cnt[NG];

__device__ __forceinline__ void red_add(float* p, float v) {
    asm volatile("red.global.add.f32 [%0], %1;" :: "l"(p), "f"(v) : "memory");
}

// ---------------- clear (runs once per launch) ----------------
__global__ void clear_all() {
    int i = blockIdx.x * blockDim.x + threadIdx.x;
    if (i < NN) g_deg[i] = 0;
    if (i < NG * 32) g_sums[i] = 0.f;
    if (i < NG) g_cnt[i] = 0.f;
}

// ---------------- counting sort: histogram ----------------
__global__ void hist(const int* __restrict__ dst) {
    int e = blockIdx.x * blockDim.x + threadIdx.x;
    if (e < NE) atomicAdd(&g_deg[dst[e]], 1);
}

// ---------------- block-level exclusive scan ----------------
__global__ void scan_block() {
    __shared__ int sh[256];
    int tid = threadIdx.x;
    int i = blockIdx.x * 256 + tid;
    int v = (i < NN) ? g_deg[i] : 0;
    sh[tid] = v;
    __syncthreads();
    for (int off = 1; off < 256; off <<= 1) {
        int t = (tid >= off) ? sh[tid - off] : 0;
        __syncthreads();
        sh[tid] += t;
        __syncthreads();
    }
    if (i < NN) g_row[i] = sh[tid] - v;        // exclusive within block
    if (tid == 255) g_part[blockIdx.x] = sh[255];
}

__global__ void scan_part() {
    __shared__ int sh[512];
    int tid = threadIdx.x;
    int v = (tid < NBLK) ? g_part[tid] : 0;
    sh[tid] = v;
    __syncthreads();
    for (int off = 1; off < 512; off <<= 1) {
        int t = (tid >= off) ? sh[tid - off] : 0;
        __syncthreads();
        sh[tid] += t;
        __syncthreads();
    }
    if (tid < NBLK) g_part[tid] = sh[tid] - v;  // exclusive block offsets
}

__global__ void scan_add() {
    int i = blockIdx.x * blockDim.x + threadIdx.x;
    if (i >= NN) return;
    int r = g_row[i] + g_part[i >> 8];
    g_row[i] = r;
    g_cur[i] = r;
}

// ---------------- counting sort: scatter ----------------
__global__ void scatter(const int* __restrict__ src, const int* __restrict__ dst) {
    int e = blockIdx.x * blockDim.x + threadIdx.x;
    if (e >= NE) return;
    int d = dst[e];
    int p = atomicAdd(&g_cur[d], 1);
    g_ssrc[p] = src[e];
}

// ---------------- node linear, layer 1: x[N,11] -> q,kv,skip (d=16) ----------------
__global__ void lin1(const float* __restrict__ x,
                     const float* __restrict__ Wq, const float* __restrict__ bq,
                     const float* __restrict__ Wk, const float* __restrict__ bk,
                     const float* __restrict__ Wv, const float* __restrict__ bv,
                     const float* __restrict__ Ws, const float* __restrict__ bs) {
    __shared__ float sW[4][11 * 16];
    __shared__ float sB[4][16];
    {
        const float* Wp[4] = {Wq, Wk, Wv, Ws};
        const float* Bp[4] = {bq, bk, bv, bs};
        for (int t = threadIdx.x; t < 4 * 176; t += blockDim.x)
            sW[t / 176][t % 176] = Wp[t / 176][t % 176];
        for (int t = threadIdx.x; t < 4 * 16; t += blockDim.x)
            sB[t / 16][t % 16] = Bp[t / 16][t % 16];
    }
    __syncthreads();
    int n = blockIdx.x * blockDim.x + threadIdx.x;
    if (n >= NN) return;
    float xv[11];
#pragma unroll
    for (int i = 0; i < 11; i++) xv[i] = x[n * 11 + i];
#pragma unroll
    for (int j = 0; j < 16; j++) {
        float aq = sB[0][j], ak = sB[1][j], av = sB[2][j], as = sB[3][j];
#pragma unroll
        for (int i = 0; i < 11; i++) {
            float xi = xv[i];
            aq += xi * sW[0][i * 16 + j];
            ak += xi * sW[1][i * 16 + j];
            av += xi * sW[2][i * 16 + j];
            as += xi * sW[3][i * 16 + j];
        }
        g_q[n * 16 + j] = aq;
        g_kv[n * 32 + j] = ak;
        g_kv[n * 32 + 16 + j] = av;
        g_skip[n * 16 + j] = as;
    }
}

// ---------------- node linear, layer 2: h[N,16] -> q,kv,skip (d=32) ----------------
__global__ void lin2(const float* __restrict__ Wq, const float* __restrict__ bq,
                     const float* __restrict__ Wk, const float* __restrict__ bk,
                     const float* __restrict__ Wv, const float* __restrict__ bv,
                     const float* __restrict__ Ws, const float* __restrict__ bs) {
    __shared__ float sW[4][16 * 32];
    __shared__ float sB[4][32];
    {
        const float* Wp[4] = {Wq, Wk, Wv, Ws};
        const float* Bp[4] = {bq, bk, bv, bs};
        for (int t = threadIdx.x; t < 4 * 512; t += blockDim.x)
            sW[t / 512][t % 512] = Wp[t / 512][t % 512];
        for (int t = threadIdx.x; t < 4 * 32; t += blockDim.x)
            sB[t / 32][t % 32] = Bp[t / 32][t % 32];
    }
    __syncthreads();
    int n = blockIdx.x * blockDim.x + threadIdx.x;
    if (n >= NN) return;
    float xv[16];
#pragma unroll
    for (int i = 0; i < 16; i++) xv[i] = g_h[n * 16 + i];
#pragma unroll
    for (int j = 0; j < 32; j++) {
        float aq = sB[0][j], ak = sB[1][j], av = sB[2][j], as = sB[3][j];
#pragma unroll
        for (int i = 0; i < 16; i++) {
            float xi = xv[i];
            aq += xi * sW[0][i * 32 + j];
            ak += xi * sW[1][i * 32 + j];
            av += xi * sW[2][i * 32 + j];
            as += xi * sW[3][i * 32 + j];
        }
        g_q[n * 32 + j] = aq;
        g_kv[n * 64 + j] = ak;
        g_kv[n * 64 + 32 + j] = av;
        g_skip[n * 32 + j] = as;
    }
}

// ---------------- conv layer 1 (d=16): warp per dst node, 2 edges/iter ----------------
__global__ void conv1() {
    int w = (blockIdx.x * blockDim.x + threadIdx.x) >> 5;
    if (w >= NN) return;
    int lane = threadIdx.x & 31;
    int half = lane >> 4;
    int l = lane & 15;
    int row = g_row[w];
    int deg = g_deg[w];
    float q = g_q[w * 16 + l] * 0.25f;   // fold 1/sqrt(16)
    float acc = 0.f, den = 0.f;
    for (int base = 0; base < deg; base += 32) {
        int sv = (base + lane < deg) ? g_ssrc[row + base + lane] : 0;
        int lim = min(32, deg - base);
        for (int j = 0; j < lim; j += 2) {
            int myj = j + half;
            int s = __shfl_sync(0xFFFFFFFFu, sv, myj);
            bool ok = myj < lim;
            int ss = ok ? s : 0;
            float kk = g_kv[ss * 32 + l];
            float dot = q * kk;
            dot += __shfl_xor_sync(0xFFFFFFFFu, dot, 8);
            dot += __shfl_xor_sync(0xFFFFFFFFu, dot, 4);
            dot += __shfl_xor_sync(0xFFFFFFFFu, dot, 2);
            dot += __shfl_xor_sync(0xFFFFFFFFu, dot, 1);
            float ev = ok ? __expf(dot) : 0.f;
            den += ev;
            acc += ev * g_kv[ss * 32 + 16 + l];
        }
    }
    acc += __shfl_xor_sync(0xFFFFFFFFu, acc, 16);
    den += __shfl_xor_sync(0xFFFFFFFFu, den, 16);
    if (half == 0) {
        float o = acc / fmaxf(den, 1e-16f) + g_skip[w * 16 + l];
        g_h[w * 16 + l] = fmaxf(o, 0.f);
    }
}

// ---------------- conv layer 2 (d=32): warp per dst node + fused pool ----------------
__global__ void conv2(const int* __restrict__ batch) {
    int w = (blockIdx.x * blockDim.x + threadIdx.x) >> 5;
    if (w >= NN) return;
    int lane = threadIdx.x & 31;
    int row = g_row[w];
    int deg = g_deg[w];
    float q = g_q[w * 32 + lane] * 0.1767766953f;   // fold 1/sqrt(32)
    float acc = 0.f, den = 0.f;
    for (int base = 0; base < deg; base += 32) {
        int sv = (base + lane < deg) ? g_ssrc[row + base + lane] : 0;
        int lim = min(32, deg - base);
        int j = 0;
        for (; j + 1 < lim; j += 2) {
            int s0 = __shfl_sync(0xFFFFFFFFu, sv, j);
            int s1 = __shfl_sync(0xFFFFFFFFu, sv, j + 1);
            float k0 = g_kv[s0 * 64 + lane];
            float k1 = g_kv[s1 * 64 + lane];
            float v0 = g_kv[s0 * 64 + 32 + lane];
            float v1 = g_kv[s1 * 64 + 32 + lane];
            float d0 = q * k0, d1 = q * k1;
            d0 += __shfl_xor_sync(0xFFFFFFFFu, d0, 16);
            d1 += __shfl_xor_sync(0xFFFFFFFFu, d1, 16);
            d0 += __shfl_xor_sync(0xFFFFFFFFu, d0, 8);
            d1 += __shfl_xor_sync(0xFFFFFFFFu, d1, 8);
            d0 += __shfl_xor_sync(0xFFFFFFFFu, d0, 4);
            d1 += __shfl_xor_sync(0xFFFFFFFFu, d1, 4);
            d0 += __shfl_xor_sync(0xFFFFFFFFu, d0, 2);
            d1 += __shfl_xor_sync(0xFFFFFFFFu, d1, 2);
            d0 += __shfl_xor_sync(0xFFFFFFFFu, d0, 1);
            d1 += __shfl_xor_sync(0xFFFFFFFFu, d1, 1);
            float e0 = __expf(d0);
            float e1 = __expf(d1);
            den += e0 + e1;
            acc += e0 * v0 + e1 * v1;
        }
        if (j < lim) {
            int s0 = __shfl_sync(0xFFFFFFFFu, sv, j);
            float k0 = g_kv[s0 * 64 + lane];
            float v0 = g_kv[s0 * 64 + 32 + lane];
            float d0 = q * k0;
            d0 += __shfl_xor_sync(0xFFFFFFFFu, d0, 16);
            d0 += __shfl_xor_sync(0xFFFFFFFFu, d0, 8);
            d0 += __shfl_xor_sync(0xFFFFFFFFu, d0, 4);
            d0 += __shfl_xor_sync(0xFFFFFFFFu, d0, 2);
            d0 += __shfl_xor_sync(0xFFFFFFFFu, d0, 1);
            float e0 = __expf(d0);
            den += e0;
            acc += e0 * v0;
        }
    }
    float val = acc / fmaxf(den, 1e-16f) + g_skip[w * 32 + lane];
    val = fmaxf(val, 0.f);
    int g = batch[w];
    red_add(&g_sums[g * 32 + lane], val);
    if (lane == 0) red_add(&g_cnt[g], 1.f);
}

// ---------------- final MLP: g[1000,32] -> 64 relu -> 1 ----------------
__global__ void final_mlp(const float* __restrict__ Wf1, const float* __restrict__ bf1,
                          const float* __restrict__ Wf2, const float* __restrict__ bf2,
                          float* __restrict__ out) {
    __shared__ float sW1[32 * 64];
    __shared__ float sB1[64];
    __shared__ float sW2[64];
    __shared__ float sB2;
    for (int t = threadIdx.x; t < 32 * 64; t += blockDim.x) sW1[t] = Wf1[t];
    for (int t = threadIdx.x; t < 64; t += blockDim.x) { sB1[t] = bf1[t]; sW2[t] = Wf2[t]; }
    if (threadIdx.x == 0) sB2 = bf2[0];
    __syncthreads();
    int g = blockIdx.x * blockDim.x + threadIdx.x;
    if (g >= NG) return;
    float cnt = fmaxf(g_cnt[g], 1.f);
    float gin[32];
#pragma unroll
    for (int i = 0; i < 32; i++) gin[i] = g_sums[g * 32 + i] / cnt;
    float acc2 = sB2;
#pragma unroll
    for (int j = 0; j < 64; j++) {
        float a = sB1[j];
#pragma unroll
        for (int i = 0; i < 32; i++) a += gin[i] * sW1[i * 64 + j];
        acc2 += fmaxf(a, 0.f) * sW2[j];
    }
    out[g] = acc2;
}

// ---------------- host launch ----------------
extern "C" void kernel_launch(void* const* d_in, const int* in_sizes, int n_in,
                              void* d_out, int out_size) {
    const float* x = (const float*)d_in[0];
    const int* eidx = (const int*)d_in[1];   // int32 (JAX x64 disabled)
    const int* src = eidx;
    const int* dst = eidx + NE;
    const int* batch = (const int*)d_in[2];
    const float *Wq1 = (const float*)d_in[3], *bq1 = (const float*)d_in[4];
    const float *Wk1 = (const float*)d_in[5], *bk1 = (const float*)d_in[6];
    const float *Wv1 = (const float*)d_in[7], *bv1 = (const float*)d_in[8];
    const float *Ws1 = (const float*)d_in[9], *bs1 = (const float*)d_in[10];
    const float *Wq2 = (const float*)d_in[11], *bq2 = (const float*)d_in[12];
    const float *Wk2 = (const float*)d_in[13], *bk2 = (const float*)d_in[14];
    const float *Wv2 = (const float*)d_in[15], *bv2 = (const float*)d_in[16];
    const float *Ws2 = (const float*)d_in[17], *bs2 = (const float*)d_in[18];
    const float *Wf1 = (const float*)d_in[19], *bf1 = (const float*)d_in[20];
    const float *Wf2 = (const float*)d_in[21], *bf2 = (const float*)d_in[22];
    float* out = (float*)d_out;

    const int EB = (NE + 255) / 256;
    const int NB = (NN + 255) / 256;
    const int WB = (NN * 32 + 255) / 256;   // warp-per-node grids

    // ---- CSR build (shared by both layers) ----
    clear_all<<<NB, 256>>>();
    hist<<<EB, 256>>>(dst);
    scan_block<<<NBLK, 256>>>();
    scan_part<<<1, 512>>>();
    scan_add<<<NB, 256>>>();
    scatter<<<EB, 256>>>(src, dst);

    // ---- layer 1 ----
    lin1<<<NB, 256>>>(x, Wq1, bq1, Wk1, bk1, Wv1, bv1, Ws1, bs1);
    conv1<<<WB, 256>>>();

    // ---- layer 2 (+ fused mean-pool accumulate) ----
    lin2<<<NB, 256>>>(Wq2, bq2, Wk2, bk2, Wv2, bv2, Ws2, bs2);
    conv2<<<WB, 256>>>(batch);

    // ---- head ----
    final_mlp<<<(NG + 255) / 256, 256>>>(Wf1, bf1, Wf2, bf2, out);
}

// round 6
// speedup vs baseline: 2.1499x; 1.0641x over previous
#include <cuda_runtime.h>

#define NN 100000
#define NE 3200000
#define NG 1000
#define NBLK ((NN + 255) / 256)   // 391

// ---------------- scratch (device globals; no allocation allowed) ----------------
__device__ int   g_deg[NN];
__device__ int   g_row[NN];
__device__ int   g_cur[NN];
__device__ int   g_part[512];
__device__ int   g_ssrc[NE];       // src ids sorted by dst
__device__ float g_q[NN * 32];     // pre-scaled by 1/sqrt(d)
__device__ float g_kv[NN * 64];    // element-interleaved (k_j, v_j) pairs
__device__ float g_skip[NN * 32];
__device__ float g_h[NN * 16];
__device__ float g_sums[NG * 32];
__device__ float g_cnt[NG];

__device__ __forceinline__ void red_add(float* p, float v) {
    asm volatile("red.global.add.f32 [%0], %1;" :: "l"(p), "f"(v) : "memory");
}

// ---------------- clear ----------------
__global__ void clear_all() {
    int i = blockIdx.x * blockDim.x + threadIdx.x;
    if (i < NN) g_deg[i] = 0;
    if (i < NG * 32) g_sums[i] = 0.f;
    if (i < NG) g_cnt[i] = 0.f;
}

// ---------------- counting sort ----------------
__global__ void hist(const int* __restrict__ dst) {
    int e = blockIdx.x * blockDim.x + threadIdx.x;
    if (e < NE) atomicAdd(&g_deg[dst[e]], 1);
}

__global__ void scan_block() {
    __shared__ int sh[256];
    int tid = threadIdx.x;
    int i = blockIdx.x * 256 + tid;
    int v = (i < NN) ? g_deg[i] : 0;
    sh[tid] = v;
    __syncthreads();
    for (int off = 1; off < 256; off <<= 1) {
        int t = (tid >= off) ? sh[tid - off] : 0;
        __syncthreads();
        sh[tid] += t;
        __syncthreads();
    }
    if (i < NN) g_row[i] = sh[tid] - v;
    if (tid == 255) g_part[blockIdx.x] = sh[255];
}

__global__ void scan_part() {
    __shared__ int sh[512];
    int tid = threadIdx.x;
    int v = (tid < NBLK) ? g_part[tid] : 0;
    sh[tid] = v;
    __syncthreads();
    for (int off = 1; off < 512; off <<= 1) {
        int t = (tid >= off) ? sh[tid - off] : 0;
        __syncthreads();
        sh[tid] += t;
        __syncthreads();
    }
    if (tid < NBLK) g_part[tid] = sh[tid] - v;
}

__global__ void scan_add() {
    int i = blockIdx.x * blockDim.x + threadIdx.x;
    if (i >= NN) return;
    int r = g_row[i] + g_part[i >> 8];
    g_row[i] = r;
    g_cur[i] = r;
}

__global__ void scatter(const int* __restrict__ src, const int* __restrict__ dst) {
    int e = blockIdx.x * blockDim.x + threadIdx.x;
    if (e >= NE) return;
    int d = dst[e];
    int p = atomicAdd(&g_cur[d], 1);
    g_ssrc[p] = src[e];
}

// ---------------- node linear, layer 1: x[N,11] -> q,kv,skip (d=16) ----------------
__global__ void lin1(const float* __restrict__ x,
                     const float* __restrict__ Wq, const float* __restrict__ bq,
                     const float* __restrict__ Wk, const float* __restrict__ bk,
                     const float* __restrict__ Wv, const float* __restrict__ bv,
                     const float* __restrict__ Ws, const float* __restrict__ bs) {
    __shared__ float sW[4][11 * 16];
    __shared__ float sB[4][16];
    {
        const float* Wp[4] = {Wq, Wk, Wv, Ws};
        const float* Bp[4] = {bq, bk, bv, bs};
        for (int t = threadIdx.x; t < 4 * 176; t += blockDim.x) {
            int m = t / 176;
            float w = Wp[m][t % 176];
            sW[m][t % 176] = (m == 0) ? w * 0.25f : w;   // fold 1/sqrt(16) into Wq
        }
        for (int t = threadIdx.x; t < 4 * 16; t += blockDim.x) {
            int m = t / 16;
            float b = Bp[m][t % 16];
            sB[m][t % 16] = (m == 0) ? b * 0.25f : b;
        }
    }
    __syncthreads();
    int n = blockIdx.x * blockDim.x + threadIdx.x;
    if (n >= NN) return;
    float xv[11];
#pragma unroll
    for (int i = 0; i < 11; i++) xv[i] = x[n * 11 + i];
#pragma unroll
    for (int j = 0; j < 16; j++) {
        float aq = sB[0][j], ak = sB[1][j], av = sB[2][j], as = sB[3][j];
#pragma unroll
        for (int i = 0; i < 11; i++) {
            float xi = xv[i];
            aq += xi * sW[0][i * 16 + j];
            ak += xi * sW[1][i * 16 + j];
            av += xi * sW[2][i * 16 + j];
            as += xi * sW[3][i * 16 + j];
        }
        g_q[n * 16 + j] = aq;
        g_kv[n * 32 + 2 * j] = ak;       // interleaved (k_j, v_j)
        g_kv[n * 32 + 2 * j + 1] = av;
        g_skip[n * 16 + j] = as;
    }
}

// ---------------- node linear, layer 2: h[N,16] -> q,kv,skip (d=32) ----------------
__global__ void lin2(const float* __restrict__ Wq, const float* __restrict__ bq,
                     const float* __restrict__ Wk, const float* __restrict__ bk,
                     const float* __restrict__ Wv, const float* __restrict__ bv,
                     const float* __restrict__ Ws, const float* __restrict__ bs) {
    __shared__ float sW[4][16 * 32];
    __shared__ float sB[4][32];
    {
        const float* Wp[4] = {Wq, Wk, Wv, Ws};
        const float* Bp[4] = {bq, bk, bv, bs};
        const float sc = 0.1767766953f;   // 1/sqrt(32)
        for (int t = threadIdx.x; t < 4 * 512; t += blockDim.x) {
            int m = t / 512;
            float w = Wp[m][t % 512];
            sW[m][t % 512] = (m == 0) ? w * sc : w;
        }
        for (int t = threadIdx.x; t < 4 * 32; t += blockDim.x) {
            int m = t / 32;
            float b = Bp[m][t % 32];
            sB[m][t % 32] = (m == 0) ? b * sc : b;
        }
    }
    __syncthreads();
    int n = blockIdx.x * blockDim.x + threadIdx.x;
    if (n >= NN) return;
    float xv[16];
#pragma unroll
    for (int i = 0; i < 16; i++) xv[i] = g_h[n * 16 + i];
#pragma unroll
    for (int j = 0; j < 32; j++) {
        float aq = sB[0][j], ak = sB[1][j], av = sB[2][j], as = sB[3][j];
#pragma unroll
        for (int i = 0; i < 16; i++) {
            float xi = xv[i];
            aq += xi * sW[0][i * 32 + j];
            ak += xi * sW[1][i * 32 + j];
            av += xi * sW[2][i * 32 + j];
            as += xi * sW[3][i * 32 + j];
        }
        g_q[n * 32 + j] = aq;
        g_kv[n * 64 + 2 * j] = ak;
        g_kv[n * 64 + 2 * j + 1] = av;
        g_skip[n * 32 + j] = as;
    }
}

// ---------------- conv layer 1 (d=16): warp per dst, 4 edges/iter (2 per half) ----------------
__global__ void conv1() {
    int w = (blockIdx.x * blockDim.x + threadIdx.x) >> 5;
    if (w >= NN) return;
    int lane = threadIdx.x & 31;
    int half = lane >> 4;
    int l = lane & 15;
    int row = g_row[w];
    int deg = g_deg[w];
    float q = g_q[w * 16 + l];   // pre-scaled
    const float2* kv = (const float2*)g_kv;   // node n: kv[n*16 + j]
    float acc = 0.f, den = 0.f;
    for (int base = 0; base < deg; base += 32) {
        int sv = (base + lane < deg) ? g_ssrc[row + base + lane] : 0;
        int lim = min(32, deg - base);
        for (int j = 0; j < lim; j += 4) {
            int j0 = j + half, j1 = j + 2 + half;
            int s0 = __shfl_sync(0xFFFFFFFFu, sv, j0);
            int s1 = __shfl_sync(0xFFFFFFFFu, sv, j1);
            bool ok0 = j0 < lim, ok1 = j1 < lim;
            float2 a0 = kv[(ok0 ? s0 : 0) * 16 + l];
            float2 a1 = kv[(ok1 ? s1 : 0) * 16 + l];
            float d0 = q * a0.x, d1 = q * a1.x;
            // interleaved 16-lane butterflies (independent chains pipeline)
            d0 += __shfl_xor_sync(0xFFFFFFFFu, d0, 8);
            d1 += __shfl_xor_sync(0xFFFFFFFFu, d1, 8);
            d0 += __shfl_xor_sync(0xFFFFFFFFu, d0, 4);
            d1 += __shfl_xor_sync(0xFFFFFFFFu, d1, 4);
            d0 += __shfl_xor_sync(0xFFFFFFFFu, d0, 2);
            d1 += __shfl_xor_sync(0xFFFFFFFFu, d1, 2);
            d0 += __shfl_xor_sync(0xFFFFFFFFu, d0, 1);
            d1 += __shfl_xor_sync(0xFFFFFFFFu, d1, 1);
            float e0 = ok0 ? __expf(d0) : 0.f;
            float e1 = ok1 ? __expf(d1) : 0.f;
            den += e0 + e1;
            acc += e0 * a0.y + e1 * a1.y;
        }
    }
    acc += __shfl_xor_sync(0xFFFFFFFFu, acc, 16);
    den += __shfl_xor_sync(0xFFFFFFFFu, den, 16);
    if (half == 0) {
        float o = acc / fmaxf(den, 1e-16f) + g_skip[w * 16 + l];
        g_h[w * 16 + l] = fmaxf(o, 0.f);
    }
}

// ---------------- conv layer 2 (d=32): warp per dst, 4 edges/iter + fused pool ----------------
__global__ void conv2(const int* __restrict__ batch) {
    int w = (blockIdx.x * blockDim.x + threadIdx.x) >> 5;
    if (w >= NN) return;
    int lane = threadIdx.x & 31;
    int row = g_row[w];
    int deg = g_deg[w];
    float q = g_q[w * 32 + lane];   // pre-scaled
    const float2* kv = (const float2*)g_kv;   // node n: kv[n*32 + j]
    float acc = 0.f, den = 0.f;
    for (int base = 0; base < deg; base += 32) {
        int sv = (base + lane < deg) ? g_ssrc[row + base + lane] : 0;
        int lim = min(32, deg - base);
        int j = 0;
        for (; j + 3 < lim; j += 4) {
            int s0 = __shfl_sync(0xFFFFFFFFu, sv, j);
            int s1 = __shfl_sync(0xFFFFFFFFu, sv, j + 1);
            int s2 = __shfl_sync(0xFFFFFFFFu, sv, j + 2);
            int s3 = __shfl_sync(0xFFFFFFFFu, sv, j + 3);
            float2 a0 = kv[s0 * 32 + lane];
            float2 a1 = kv[s1 * 32 + lane];
            float2 a2 = kv[s2 * 32 + lane];
            float2 a3 = kv[s3 * 32 + lane];
            float d0 = q * a0.x, d1 = q * a1.x, d2 = q * a2.x, d3 = q * a3.x;
            // 4 interleaved butterflies — chains overlap, SHFL throughput-bound
            d0 += __shfl_xor_sync(0xFFFFFFFFu, d0, 16);
            d1 += __shfl_xor_sync(0xFFFFFFFFu, d1, 16);
            d2 += __shfl_xor_sync(0xFFFFFFFFu, d2, 16);
            d3 += __shfl_xor_sync(0xFFFFFFFFu, d3, 16);
            d0 += __shfl_xor_sync(0xFFFFFFFFu, d0, 8);
            d1 += __shfl_xor_sync(0xFFFFFFFFu, d1, 8);
            d2 += __shfl_xor_sync(0xFFFFFFFFu, d2, 8);
            d3 += __shfl_xor_sync(0xFFFFFFFFu, d3, 8);
            d0 += __shfl_xor_sync(0xFFFFFFFFu, d0, 4);
            d1 += __shfl_xor_sync(0xFFFFFFFFu, d1, 4);
            d2 += __shfl_xor_sync(0xFFFFFFFFu, d2, 4);
            d3 += __shfl_xor_sync(0xFFFFFFFFu, d3, 4);
            d0 += __shfl_xor_sync(0xFFFFFFFFu, d0, 2);
            d1 += __shfl_xor_sync(0xFFFFFFFFu, d1, 2);
            d2 += __shfl_xor_sync(0xFFFFFFFFu, d2, 2);
            d3 += __shfl_xor_sync(0xFFFFFFFFu, d3, 2);
            d0 += __shfl_xor_sync(0xFFFFFFFFu, d0, 1);
            d1 += __shfl_xor_sync(0xFFFFFFFFu, d1, 1);
            d2 += __shfl_xor_sync(0xFFFFFFFFu, d2, 1);
            d3 += __shfl_xor_sync(0xFFFFFFFFu, d3, 1);
            float e0 = __expf(d0), e1 = __expf(d1);
            float e2 = __expf(d2), e3 = __expf(d3);
            den += (e0 + e1) + (e2 + e3);
            acc += e0 * a0.y + e1 * a1.y + e2 * a2.y + e3 * a3.y;
        }
        for (; j < lim; j++) {
            int s0 = __shfl_sync(0xFFFFFFFFu, sv, j);
            float2 a0 = kv[s0 * 32 + lane];
            float d0 = q * a0.x;
            d0 += __shfl_xor_sync(0xFFFFFFFFu, d0, 16);
            d0 += __shfl_xor_sync(0xFFFFFFFFu, d0, 8);
            d0 += __shfl_xor_sync(0xFFFFFFFFu, d0, 4);
            d0 += __shfl_xor_sync(0xFFFFFFFFu, d0, 2);
            d0 += __shfl_xor_sync(0xFFFFFFFFu, d0, 1);
            float e0 = __expf(d0);
            den += e0;
            acc += e0 * a0.y;
        }
    }
    float val = acc / fmaxf(den, 1e-16f) + g_skip[w * 32 + lane];
    val = fmaxf(val, 0.f);
    int g = batch[w];
    red_add(&g_sums[g * 32 + lane], val);
    if (lane == 0) red_add(&g_cnt[g], 1.f);
}

// ---------------- final MLP ----------------
__global__ void final_mlp(const float* __restrict__ Wf1, const float* __restrict__ bf1,
                          const float* __restrict__ Wf2, const float* __restrict__ bf2,
                          float* __restrict__ out) {
    __shared__ float sW1[32 * 64];
    __shared__ float sB1[64];
    __shared__ float sW2[64];
    __shared__ float sB2;
    for (int t = threadIdx.x; t < 32 * 64; t += blockDim.x) sW1[t] = Wf1[t];
    for (int t = threadIdx.x; t < 64; t += blockDim.x) { sB1[t] = bf1[t]; sW2[t] = Wf2[t]; }
    if (threadIdx.x == 0) sB2 = bf2[0];
    __syncthreads();
    int g = blockIdx.x * blockDim.x + threadIdx.x;
    if (g >= NG) return;
    float cnt = fmaxf(g_cnt[g], 1.f);
    float gin[32];
#pragma unroll
    for (int i = 0; i < 32; i++) gin[i] = g_sums[g * 32 + i] / cnt;
    float acc2 = sB2;
#pragma unroll
    for (int j = 0; j < 64; j++) {
        float a = sB1[j];
#pragma unroll
        for (int i = 0; i < 32; i++) a += gin[i] * sW1[i * 64 + j];
        acc2 += fmaxf(a, 0.f) * sW2[j];
    }
    out[g] = acc2;
}

// ---------------- host launch ----------------
extern "C" void kernel_launch(void* const* d_in, const int* in_sizes, int n_in,
                              void* d_out, int out_size) {
    const float* x = (const float*)d_in[0];
    const int* eidx = (const int*)d_in[1];
    const int* src = eidx;
    const int* dst = eidx + NE;
    const int* batch = (const int*)d_in[2];
    const float *Wq1 = (const float*)d_in[3], *bq1 = (const float*)d_in[4];
    const float *Wk1 = (const float*)d_in[5], *bk1 = (const float*)d_in[6];
    const float *Wv1 = (const float*)d_in[7], *bv1 = (const float*)d_in[8];
    const float *Ws1 = (const float*)d_in[9], *bs1 = (const float*)d_in[10];
    const float *Wq2 = (const float*)d_in[11], *bq2 = (const float*)d_in[12];
    const float *Wk2 = (const float*)d_in[13], *bk2 = (const float*)d_in[14];
    const float *Wv2 = (const float*)d_in[15], *bv2 = (const float*)d_in[16];
    const float *Ws2 = (const float*)d_in[17], *bs2 = (const float*)d_in[18];
    const float *Wf1 = (const float*)d_in[19], *bf1 = (const float*)d_in[20];
    const float *Wf2 = (const float*)d_in[21], *bf2 = (const float*)d_in[22];
    float* out = (float*)d_out;

    const int EB = (NE + 255) / 256;
    const int NB = (NN + 255) / 256;
    const int WB = (NN * 32 + 255) / 256;

    clear_all<<<NB, 256>>>();
    hist<<<EB, 256>>>(dst);
    scan_block<<<NBLK, 256>>>();
    scan_part<<<1, 512>>>();
    scan_add<<<NB, 256>>>();
    scatter<<<EB, 256>>>(src, dst);

    lin1<<<NB, 256>>>(x, Wq1, bq1, Wk1, bk1, Wv1, bv1, Ws1, bs1);
    conv1<<<WB, 256>>>();

    lin2<<<NB, 256>>>(Wq2, bq2, Wk2, bk2, Wv2, bv2, Ws2, bs2);
    conv2<<<WB, 256>>>(batch);

    final_mlp<<<(NG + 255) / 256, 256>>>(Wf1, bf1, Wf2, bf2, out);
}

// round 7
// speedup vs baseline: 2.5602x; 1.1909x over previous
#include <cuda_runtime.h>

#define NN 100000
#define NE 3200000
#define NG 1000
#define NBLK ((NN + 255) / 256)   // 391

// ---------------- scratch (device globals; no allocation allowed) ----------------
__device__ int   g_deg[NN];
__device__ int   g_row[NN];
__device__ int   g_cur[NN];
__device__ int   g_part[512];
__device__ int   g_ssrc[NE];       // src ids sorted by dst
__device__ float g_q[NN * 32];     // pre-scaled by 1/sqrt(d)
__device__ float g_kv[NN * 64];    // float4-packed (k_2p, v_2p, k_2p+1, v_2p+1)
__device__ float g_skip[NN * 32];
__device__ float g_h[NN * 16];
__device__ float g_sums[NG * 32];
__device__ float g_cnt[NG];

__device__ __forceinline__ void red_add(float* p, float v) {
    asm volatile("red.global.add.f32 [%0], %1;" :: "l"(p), "f"(v) : "memory");
}
__device__ __forceinline__ void red_add2(float* p, float a, float b) {
    asm volatile("red.global.add.v2.f32 [%0], {%1,%2};" :: "l"(p), "f"(a), "f"(b) : "memory");
}

// ---------------- clear ----------------
__global__ void clear_all() {
    int i = blockIdx.x * blockDim.x + threadIdx.x;
    if (i < NN) g_deg[i] = 0;
    if (i < NG * 32) g_sums[i] = 0.f;
    if (i < NG) g_cnt[i] = 0.f;
}

// ---------------- counting sort ----------------
__global__ void hist(const int* __restrict__ dst) {
    int e = blockIdx.x * blockDim.x + threadIdx.x;
    if (e < NE) atomicAdd(&g_deg[dst[e]], 1);
}

__global__ void scan_block() {
    __shared__ int sh[256];
    int tid = threadIdx.x;
    int i = blockIdx.x * 256 + tid;
    int v = (i < NN) ? g_deg[i] : 0;
    sh[tid] = v;
    __syncthreads();
    for (int off = 1; off < 256; off <<= 1) {
        int t = (tid >= off) ? sh[tid - off] : 0;
        __syncthreads();
        sh[tid] += t;
        __syncthreads();
    }
    if (i < NN) g_row[i] = sh[tid] - v;
    if (tid == 255) g_part[blockIdx.x] = sh[255];
}

__global__ void scan_part() {
    __shared__ int sh[512];
    int tid = threadIdx.x;
    int v = (tid < NBLK) ? g_part[tid] : 0;
    sh[tid] = v;
    __syncthreads();
    for (int off = 1; off < 512; off <<= 1) {
        int t = (tid >= off) ? sh[tid - off] : 0;
        __syncthreads();
        sh[tid] += t;
        __syncthreads();
    }
    if (tid < NBLK) g_part[tid] = sh[tid] - v;
}

__global__ void scan_add() {
    int i = blockIdx.x * blockDim.x + threadIdx.x;
    if (i >= NN) return;
    int r = g_row[i] + g_part[i >> 8];
    g_row[i] = r;
    g_cur[i] = r;
}

__global__ void scatter(const int* __restrict__ src, const int* __restrict__ dst) {
    int e = blockIdx.x * blockDim.x + threadIdx.x;
    if (e >= NE) return;
    int d = dst[e];
    int p = atomicAdd(&g_cur[d], 1);
    g_ssrc[p] = src[e];
}

// ---------------- node linear, layer 1: x[N,11] -> q,kv,skip (d=16) ----------------
__global__ void lin1(const float* __restrict__ x,
                     const float* __restrict__ Wq, const float* __restrict__ bq,
                     const float* __restrict__ Wk, const float* __restrict__ bk,
                     const float* __restrict__ Wv, const float* __restrict__ bv,
                     const float* __restrict__ Ws, const float* __restrict__ bs) {
    __shared__ float sW[4][11 * 16];
    __shared__ float sB[4][16];
    {
        const float* Wp[4] = {Wq, Wk, Wv, Ws};
        const float* Bp[4] = {bq, bk, bv, bs};
        for (int t = threadIdx.x; t < 4 * 176; t += blockDim.x) {
            int m = t / 176;
            float w = Wp[m][t % 176];
            sW[m][t % 176] = (m == 0) ? w * 0.25f : w;   // fold 1/sqrt(16) into Wq
        }
        for (int t = threadIdx.x; t < 4 * 16; t += blockDim.x) {
            int m = t / 16;
            float b = Bp[m][t % 16];
            sB[m][t % 16] = (m == 0) ? b * 0.25f : b;
        }
    }
    __syncthreads();
    int n = blockIdx.x * blockDim.x + threadIdx.x;
    if (n >= NN) return;
    float xv[11];
#pragma unroll
    for (int i = 0; i < 11; i++) xv[i] = x[n * 11 + i];
#pragma unroll
    for (int j = 0; j < 16; j++) {
        float aq = sB[0][j], ak = sB[1][j], av = sB[2][j], as = sB[3][j];
#pragma unroll
        for (int i = 0; i < 11; i++) {
            float xi = xv[i];
            aq += xi * sW[0][i * 16 + j];
            ak += xi * sW[1][i * 16 + j];
            av += xi * sW[2][i * 16 + j];
            as += xi * sW[3][i * 16 + j];
        }
        g_q[n * 16 + j] = aq;
        // float4 packing: (k_2p, v_2p, k_2p+1, v_2p+1), node stride 32 floats
        g_kv[n * 32 + (j >> 1) * 4 + (j & 1) * 2] = ak;
        g_kv[n * 32 + (j >> 1) * 4 + (j & 1) * 2 + 1] = av;
        g_skip[n * 16 + j] = as;
    }
}

// ---------------- node linear, layer 2: h[N,16] -> q,kv,skip (d=32) ----------------
__global__ void lin2(const float* __restrict__ Wq, const float* __restrict__ bq,
                     const float* __restrict__ Wk, const float* __restrict__ bk,
                     const float* __restrict__ Wv, const float* __restrict__ bv,
                     const float* __restrict__ Ws, const float* __restrict__ bs) {
    __shared__ float sW[4][16 * 32];
    __shared__ float sB[4][32];
    {
        const float* Wp[4] = {Wq, Wk, Wv, Ws};
        const float* Bp[4] = {bq, bk, bv, bs};
        const float sc = 0.1767766953f;   // 1/sqrt(32)
        for (int t = threadIdx.x; t < 4 * 512; t += blockDim.x) {
            int m = t / 512;
            float w = Wp[m][t % 512];
            sW[m][t % 512] = (m == 0) ? w * sc : w;
        }
        for (int t = threadIdx.x; t < 4 * 32; t += blockDim.x) {
            int m = t / 32;
            float b = Bp[m][t % 32];
            sB[m][t % 32] = (m == 0) ? b * sc : b;
        }
    }
    __syncthreads();
    int n = blockIdx.x * blockDim.x + threadIdx.x;
    if (n >= NN) return;
    float xv[16];
#pragma unroll
    for (int i = 0; i < 16; i++) xv[i] = g_h[n * 16 + i];
#pragma unroll
    for (int j = 0; j < 32; j++) {
        float aq = sB[0][j], ak = sB[1][j], av = sB[2][j], as = sB[3][j];
#pragma unroll
        for (int i = 0; i < 16; i++) {
            float xi = xv[i];
            aq += xi * sW[0][i * 32 + j];
            ak += xi * sW[1][i * 32 + j];
            av += xi * sW[2][i * 32 + j];
            as += xi * sW[3][i * 32 + j];
        }
        g_q[n * 32 + j] = aq;
        // float4 packing, node stride 64 floats
        g_kv[n * 64 + (j >> 1) * 4 + (j & 1) * 2] = ak;
        g_kv[n * 64 + (j >> 1) * 4 + (j & 1) * 2 + 1] = av;
        g_skip[n * 32 + j] = as;
    }
}

// ---------------- conv layer 1 (d=16): 8 lanes/edge, 4 edges per warp slot ----------------
__global__ void conv1() {
    int w = (blockIdx.x * blockDim.x + threadIdx.x) >> 5;
    if (w >= NN) return;
    int lane = threadIdx.x & 31;
    int quarter = lane >> 3;          // 0..3 : which edge in the group
    int l = lane & 7;                 // element pair index (elems 2l, 2l+1)
    int row = g_row[w];
    int deg = g_deg[w];
    float2 q2 = ((const float2*)g_q)[w * 8 + l];   // pre-scaled
    const float4* kv = (const float4*)g_kv;        // node n: kv[n*8 + l]
    float acc0 = 0.f, acc1 = 0.f, den = 0.f;
    for (int base = 0; base < deg; base += 32) {
        int sv = (base + lane < deg) ? g_ssrc[row + base + lane] : 0;
        int lim = min(32, deg - base);
        int j = 0;
        for (; j + 7 < lim; j += 8) {
            int sA = __shfl_sync(0xFFFFFFFFu, sv, j + quarter);
            int sB = __shfl_sync(0xFFFFFFFFu, sv, j + 4 + quarter);
            float4 a = kv[sA * 8 + l];
            float4 b = kv[sB * 8 + l];
            float dA = q2.x * a.x + q2.y * a.z;
            float dB = q2.x * b.x + q2.y * b.z;
            dA += __shfl_xor_sync(0xFFFFFFFFu, dA, 4);
            dB += __shfl_xor_sync(0xFFFFFFFFu, dB, 4);
            dA += __shfl_xor_sync(0xFFFFFFFFu, dA, 2);
            dB += __shfl_xor_sync(0xFFFFFFFFu, dB, 2);
            dA += __shfl_xor_sync(0xFFFFFFFFu, dA, 1);
            dB += __shfl_xor_sync(0xFFFFFFFFu, dB, 1);
            float eA = __expf(dA);
            float eB = __expf(dB);
            den += eA + eB;
            acc0 += eA * a.y + eB * b.y;
            acc1 += eA * a.w + eB * b.w;
        }
        for (; j < lim; j += 4) {
            bool ok = (j + quarter) < lim;
            int sA = __shfl_sync(0xFFFFFFFFu, sv, ok ? j + quarter : 0);
            float4 a = kv[(ok ? sA : 0) * 8 + l];
            float dA = q2.x * a.x + q2.y * a.z;
            dA += __shfl_xor_sync(0xFFFFFFFFu, dA, 4);
            dA += __shfl_xor_sync(0xFFFFFFFFu, dA, 2);
            dA += __shfl_xor_sync(0xFFFFFFFFu, dA, 1);
            float eA = ok ? __expf(dA) : 0.f;
            den += eA;
            acc0 += eA * a.y;
            acc1 += eA * a.w;
        }
    }
    // fold the 4 quarters (lane bits 3,4)
    acc0 += __shfl_xor_sync(0xFFFFFFFFu, acc0, 8);
    acc1 += __shfl_xor_sync(0xFFFFFFFFu, acc1, 8);
    den  += __shfl_xor_sync(0xFFFFFFFFu, den, 8);
    acc0 += __shfl_xor_sync(0xFFFFFFFFu, acc0, 16);
    acc1 += __shfl_xor_sync(0xFFFFFFFFu, acc1, 16);
    den  += __shfl_xor_sync(0xFFFFFFFFu, den, 16);
    if (quarter == 0) {
        float inv = 1.0f / fmaxf(den, 1e-16f);
        float2 sk = ((const float2*)g_skip)[w * 8 + l];
        float2 o;
        o.x = fmaxf(acc0 * inv + sk.x, 0.f);
        o.y = fmaxf(acc1 * inv + sk.y, 0.f);
        ((float2*)g_h)[w * 8 + l] = o;
    }
}

// ---------------- conv layer 2 (d=32): 16 lanes/edge, 2 edges per warp slot + fused pool ----------------
__global__ void conv2(const int* __restrict__ batch) {
    int w = (blockIdx.x * blockDim.x + threadIdx.x) >> 5;
    if (w >= NN) return;
    int lane = threadIdx.x & 31;
    int half = lane >> 4;             // 0..1 : which edge in the pair
    int l = lane & 15;                // element pair index (elems 2l, 2l+1)
    int row = g_row[w];
    int deg = g_deg[w];
    float2 q2 = ((const float2*)g_q)[w * 16 + l];   // pre-scaled
    const float4* kv = (const float4*)g_kv;         // node n: kv[n*16 + l]
    float acc0 = 0.f, acc1 = 0.f, den = 0.f;
    for (int base = 0; base < deg; base += 32) {
        int sv = (base + lane < deg) ? g_ssrc[row + base + lane] : 0;
        int lim = min(32, deg - base);
        int j = 0;
        for (; j + 3 < lim; j += 4) {
            int sA = __shfl_sync(0xFFFFFFFFu, sv, j + half);
            int sB = __shfl_sync(0xFFFFFFFFu, sv, j + 2 + half);
            float4 a = kv[sA * 16 + l];
            float4 b = kv[sB * 16 + l];
            float dA = q2.x * a.x + q2.y * a.z;
            float dB = q2.x * b.x + q2.y * b.z;
            dA += __shfl_xor_sync(0xFFFFFFFFu, dA, 8);
            dB += __shfl_xor_sync(0xFFFFFFFFu, dB, 8);
            dA += __shfl_xor_sync(0xFFFFFFFFu, dA, 4);
            dB += __shfl_xor_sync(0xFFFFFFFFu, dB, 4);
            dA += __shfl_xor_sync(0xFFFFFFFFu, dA, 2);
            dB += __shfl_xor_sync(0xFFFFFFFFu, dB, 2);
            dA += __shfl_xor_sync(0xFFFFFFFFu, dA, 1);
            dB += __shfl_xor_sync(0xFFFFFFFFu, dB, 1);
            float eA = __expf(dA);
            float eB = __expf(dB);
            den += eA + eB;
            acc0 += eA * a.y + eB * b.y;
            acc1 += eA * a.w + eB * b.w;
        }
        for (; j < lim; j += 2) {
            bool ok = (j + half) < lim;
            int sA = __shfl_sync(0xFFFFFFFFu, sv, ok ? j + half : 0);
            float4 a = kv[(ok ? sA : 0) * 16 + l];
            float dA = q2.x * a.x + q2.y * a.z;
            dA += __shfl_xor_sync(0xFFFFFFFFu, dA, 8);
            dA += __shfl_xor_sync(0xFFFFFFFFu, dA, 4);
            dA += __shfl_xor_sync(0xFFFFFFFFu, dA, 2);
            dA += __shfl_xor_sync(0xFFFFFFFFu, dA, 1);
            float eA = ok ? __expf(dA) : 0.f;
            den += eA;
            acc0 += eA * a.y;
            acc1 += eA * a.w;
        }
    }
    // fold the two halves (lane bit 4)
    acc0 += __shfl_xor_sync(0xFFFFFFFFu, acc0, 16);
    acc1 += __shfl_xor_sync(0xFFFFFFFFu, acc1, 16);
    den  += __shfl_xor_sync(0xFFFFFFFFu, den, 16);
    if (half == 0) {
        float inv = 1.0f / fmaxf(den, 1e-16f);
        float2 sk = ((const float2*)g_skip)[w * 16 + l];
        float v0 = fmaxf(acc0 * inv + sk.x, 0.f);
        float v1 = fmaxf(acc1 * inv + sk.y, 0.f);
        int g = batch[w];
        red_add2(&g_sums[g * 32 + 2 * l], v0, v1);
        if (l == 0) red_add(&g_cnt[g], 1.f);
    }
}

// ---------------- final MLP ----------------
__global__ void final_mlp(const float* __restrict__ Wf1, const float* __restrict__ bf1,
                          const float* __restrict__ Wf2, const float* __restrict__ bf2,
                          float* __restrict__ out) {
    __shared__ float sW1[32 * 64];
    __shared__ float sB1[64];
    __shared__ float sW2[64];
    __shared__ float sB2;
    for (int t = threadIdx.x; t < 32 * 64; t += blockDim.x) sW1[t] = Wf1[t];
    for (int t = threadIdx.x; t < 64; t += blockDim.x) { sB1[t] = bf1[t]; sW2[t] = Wf2[t]; }
    if (threadIdx.x == 0) sB2 = bf2[0];
    __syncthreads();
    int g = blockIdx.x * blockDim.x + threadIdx.x;
    if (g >= NG) return;
    float cnt = fmaxf(g_cnt[g], 1.f);
    float gin[32];
#pragma unroll
    for (int i = 0; i < 32; i++) gin[i] = g_sums[g * 32 + i] / cnt;
    float acc2 = sB2;
#pragma unroll
    for (int j = 0; j < 64; j++) {
        float a = sB1[j];
#pragma unroll
        for (int i = 0; i < 32; i++) a += gin[i] * sW1[i * 64 + j];
        acc2 += fmaxf(a, 0.f) * sW2[j];
    }
    out[g] = acc2;
}

// ---------------- host launch ----------------
extern "C" void kernel_launch(void* const* d_in, const int* in_sizes, int n_in,
                              void* d_out, int out_size) {
    const float* x = (const float*)d_in[0];
    const int* eidx = (const int*)d_in[1];
    const int* src = eidx;
    const int* dst = eidx + NE;
    const int* batch = (const int*)d_in[2];
    const float *Wq1 = (const float*)d_in[3], *bq1 = (const float*)d_in[4];
    const float *Wk1 = (const float*)d_in[5], *bk1 = (const float*)d_in[6];
    const float *Wv1 = (const float*)d_in[7], *bv1 = (const float*)d_in[8];
    const float *Ws1 = (const float*)d_in[9], *bs1 = (const float*)d_in[10];
    const float *Wq2 = (const float*)d_in[11], *bq2 = (const float*)d_in[12];
    const float *Wk2 = (const float*)d_in[13], *bk2 = (const float*)d_in[14];
    const float *Wv2 = (const float*)d_in[15], *bv2 = (const float*)d_in[16];
    const float *Ws2 = (const float*)d_in[17], *bs2 = (const float*)d_in[18];
    const float *Wf1 = (const float*)d_in[19], *bf1 = (const float*)d_in[20];
    const float *Wf2 = (const float*)d_in[21], *bf2 = (const float*)d_in[22];
    float* out = (float*)d_out;

    const int EB = (NE + 255) / 256;
    const int NB = (NN + 255) / 256;
    const int WB = (NN * 32 + 255) / 256;

    clear_all<<<NB, 256>>>();
    hist<<<EB, 256>>>(dst);
    scan_block<<<NBLK, 256>>>();
    scan_part<<<1, 512>>>();
    scan_add<<<NB, 256>>>();
    scatter<<<EB, 256>>>(src, dst);

    lin1<<<NB, 256>>>(x, Wq1, bq1, Wk1, bk1, Wv1, bv1, Ws1, bs1);
    conv1<<<WB, 256>>>();

    lin2<<<NB, 256>>>(Wq2, bq2, Wk2, bk2, Wv2, bv2, Ws2, bs2);
    conv2<<<WB, 256>>>(batch);

    final_mlp<<<(NG + 255) / 256, 256>>>(Wf1, bf1, Wf2, bf2, out);
}

// round 8
// speedup vs baseline: 2.8185x; 1.1009x over previous
#include <cuda_runtime.h>
#include <cuda_fp16.h>

#define NN 100000
#define NE 3200000
#define NG 1000
#define NBLK ((NN + 255) / 256)   // 391

// ---------------- scratch (device globals; no allocation allowed) ----------------
__device__ int     g_deg[NN];
__device__ int     g_row[NN];
__device__ int     g_cur[NN];
__device__ int     g_part[512];
__device__ int     g_ssrc[NE];      // src ids sorted by dst
__device__ float   g_q[NN * 32];    // pre-scaled by 1/sqrt(d)
__device__ __half2 g_kvh[NN * 32];  // packed (k_j, v_j) per element, fp16
__device__ float   g_skip[NN * 32];
__device__ float   g_h[NN * 16];
__device__ float   g_sums[NG * 32];
__device__ float   g_cnt[NG];

__device__ __forceinline__ void red_add(float* p, float v) {
    asm volatile("red.global.add.f32 [%0], %1;" :: "l"(p), "f"(v) : "memory");
}
__device__ __forceinline__ void red_add2(float* p, float a, float b) {
    asm volatile("red.global.add.v2.f32 [%0], {%1,%2};" :: "l"(p), "f"(a), "f"(b) : "memory");
}

// ---------------- clear ----------------
__global__ void clear_all() {
    int i = blockIdx.x * blockDim.x + threadIdx.x;
    if (i < NN) g_deg[i] = 0;
    if (i < NG * 32) g_sums[i] = 0.f;
    if (i < NG) g_cnt[i] = 0.f;
}

// ---------------- counting sort ----------------
__global__ void hist(const int* __restrict__ dst) {
    int e = blockIdx.x * blockDim.x + threadIdx.x;
    if (e < NE) atomicAdd(&g_deg[dst[e]], 1);
}

__global__ void scan_block() {
    __shared__ int sh[256];
    int tid = threadIdx.x;
    int i = blockIdx.x * 256 + tid;
    int v = (i < NN) ? g_deg[i] : 0;
    sh[tid] = v;
    __syncthreads();
    for (int off = 1; off < 256; off <<= 1) {
        int t = (tid >= off) ? sh[tid - off] : 0;
        __syncthreads();
        sh[tid] += t;
        __syncthreads();
    }
    if (i < NN) g_row[i] = sh[tid] - v;
    if (tid == 255) g_part[blockIdx.x] = sh[255];
}

__global__ void scan_part() {
    __shared__ int sh[512];
    int tid = threadIdx.x;
    int v = (tid < NBLK) ? g_part[tid] : 0;
    sh[tid] = v;
    __syncthreads();
    for (int off = 1; off < 512; off <<= 1) {
        int t = (tid >= off) ? sh[tid - off] : 0;
        __syncthreads();
        sh[tid] += t;
        __syncthreads();
    }
    if (tid < NBLK) g_part[tid] = sh[tid] - v;
}

__global__ void scan_add() {
    int i = blockIdx.x * blockDim.x + threadIdx.x;
    if (i >= NN) return;
    int r = g_row[i] + g_part[i >> 8];
    g_row[i] = r;
    g_cur[i] = r;
}

__global__ void scatter(const int* __restrict__ src, const int* __restrict__ dst) {
    int e = blockIdx.x * blockDim.x + threadIdx.x;
    if (e >= NE) return;
    int d = dst[e];
    int p = atomicAdd(&g_cur[d], 1);
    g_ssrc[p] = src[e];
}

// ---------------- node linear, layer 1: x[N,11] -> q,kv(fp16),skip (d=16) ----------------
__global__ void lin1(const float* __restrict__ x,
                     const float* __restrict__ Wq, const float* __restrict__ bq,
                     const float* __restrict__ Wk, const float* __restrict__ bk,
                     const float* __restrict__ Wv, const float* __restrict__ bv,
                     const float* __restrict__ Ws, const float* __restrict__ bs) {
    __shared__ float sW[4][11 * 16];
    __shared__ float sB[4][16];
    {
        const float* Wp[4] = {Wq, Wk, Wv, Ws};
        const float* Bp[4] = {bq, bk, bv, bs};
        for (int t = threadIdx.x; t < 4 * 176; t += blockDim.x) {
            int m = t / 176;
            float w = Wp[m][t % 176];
            sW[m][t % 176] = (m == 0) ? w * 0.25f : w;   // fold 1/sqrt(16) into Wq
        }
        for (int t = threadIdx.x; t < 4 * 16; t += blockDim.x) {
            int m = t / 16;
            float b = Bp[m][t % 16];
            sB[m][t % 16] = (m == 0) ? b * 0.25f : b;
        }
    }
    __syncthreads();
    int n = blockIdx.x * blockDim.x + threadIdx.x;
    if (n >= NN) return;
    float xv[11];
#pragma unroll
    for (int i = 0; i < 11; i++) xv[i] = x[n * 11 + i];
#pragma unroll
    for (int j = 0; j < 16; j++) {
        float aq = sB[0][j], ak = sB[1][j], av = sB[2][j], as = sB[3][j];
#pragma unroll
        for (int i = 0; i < 11; i++) {
            float xi = xv[i];
            aq += xi * sW[0][i * 16 + j];
            ak += xi * sW[1][i * 16 + j];
            av += xi * sW[2][i * 16 + j];
            as += xi * sW[3][i * 16 + j];
        }
        g_q[n * 16 + j] = aq;
        g_kvh[n * 16 + j] = __floats2half2_rn(ak, av);
        g_skip[n * 16 + j] = as;
    }
}

// ---------------- node linear, layer 2: h[N,16] -> q,kv(fp16),skip (d=32) ----------------
__global__ void lin2(const float* __restrict__ Wq, const float* __restrict__ bq,
                     const float* __restrict__ Wk, const float* __restrict__ bk,
                     const float* __restrict__ Wv, const float* __restrict__ bv,
                     const float* __restrict__ Ws, const float* __restrict__ bs) {
    __shared__ float sW[4][16 * 32];
    __shared__ float sB[4][32];
    {
        const float* Wp[4] = {Wq, Wk, Wv, Ws};
        const float* Bp[4] = {bq, bk, bv, bs};
        const float sc = 0.1767766953f;   // 1/sqrt(32)
        for (int t = threadIdx.x; t < 4 * 512; t += blockDim.x) {
            int m = t / 512;
            float w = Wp[m][t % 512];
            sW[m][t % 512] = (m == 0) ? w * sc : w;
        }
        for (int t = threadIdx.x; t < 4 * 32; t += blockDim.x) {
            int m = t / 32;
            float b = Bp[m][t % 32];
            sB[m][t % 32] = (m == 0) ? b * sc : b;
        }
    }
    __syncthreads();
    int n = blockIdx.x * blockDim.x + threadIdx.x;
    if (n >= NN) return;
    float xv[16];
#pragma unroll
    for (int i = 0; i < 16; i++) xv[i] = g_h[n * 16 + i];
#pragma unroll
    for (int j = 0; j < 32; j++) {
        float aq = sB[0][j], ak = sB[1][j], av = sB[2][j], as = sB[3][j];
#pragma unroll
        for (int i = 0; i < 16; i++) {
            float xi = xv[i];
            aq += xi * sW[0][i * 32 + j];
            ak += xi * sW[1][i * 32 + j];
            av += xi * sW[2][i * 32 + j];
            as += xi * sW[3][i * 32 + j];
        }
        g_q[n * 32 + j] = aq;
        g_kvh[n * 32 + j] = __floats2half2_rn(ak, av);
        g_skip[n * 32 + j] = as;
    }
}

// unpack one uint2 (= two half2 (k,v) pairs) into (k0,v0,k1,v1) floats
__device__ __forceinline__ float4 unpack_kv(uint2 u) {
    __half2 h0 = *reinterpret_cast<__half2*>(&u.x);
    __half2 h1 = *reinterpret_cast<__half2*>(&u.y);
    float2 f0 = __half22float2(h0);
    float2 f1 = __half22float2(h1);
    return make_float4(f0.x, f0.y, f1.x, f1.y);   // (k0, v0, k1, v1)
}

// ---------------- conv layer 1 (d=16): 8 lanes/edge, 4 edges per warp slot ----------------
__global__ void conv1() {
    int w = (blockIdx.x * blockDim.x + threadIdx.x) >> 5;
    if (w >= NN) return;
    int lane = threadIdx.x & 31;
    int quarter = lane >> 3;          // which edge in the group of 4
    int l = lane & 7;                 // element pair index (elems 2l, 2l+1)
    int row = g_row[w];
    int deg = g_deg[w];
    float2 q2 = ((const float2*)g_q)[w * 8 + l];   // pre-scaled
    const uint2* kv = (const uint2*)g_kvh;         // node n: kv[n*8 + l]
    float acc0 = 0.f, acc1 = 0.f, den = 0.f;
    for (int base = 0; base < deg; base += 32) {
        int sv = (base + lane < deg) ? g_ssrc[row + base + lane] : 0;
        int lim = min(32, deg - base);
        int j = 0;
        for (; j + 7 < lim; j += 8) {
            int sA = __shfl_sync(0xFFFFFFFFu, sv, j + quarter);
            int sB = __shfl_sync(0xFFFFFFFFu, sv, j + 4 + quarter);
            float4 a = unpack_kv(kv[sA * 8 + l]);
            float4 b = unpack_kv(kv[sB * 8 + l]);
            float dA = q2.x * a.x + q2.y * a.z;
            float dB = q2.x * b.x + q2.y * b.z;
            dA += __shfl_xor_sync(0xFFFFFFFFu, dA, 4);
            dB += __shfl_xor_sync(0xFFFFFFFFu, dB, 4);
            dA += __shfl_xor_sync(0xFFFFFFFFu, dA, 2);
            dB += __shfl_xor_sync(0xFFFFFFFFu, dB, 2);
            dA += __shfl_xor_sync(0xFFFFFFFFu, dA, 1);
            dB += __shfl_xor_sync(0xFFFFFFFFu, dB, 1);
            float eA = __expf(dA);
            float eB = __expf(dB);
            den += eA + eB;
            acc0 += eA * a.y + eB * b.y;
            acc1 += eA * a.w + eB * b.w;
        }
        for (; j < lim; j += 4) {
            bool ok = (j + quarter) < lim;
            int sA = __shfl_sync(0xFFFFFFFFu, sv, ok ? j + quarter : 0);
            float4 a = unpack_kv(kv[(ok ? sA : 0) * 8 + l]);
            float dA = q2.x * a.x + q2.y * a.z;
            dA += __shfl_xor_sync(0xFFFFFFFFu, dA, 4);
            dA += __shfl_xor_sync(0xFFFFFFFFu, dA, 2);
            dA += __shfl_xor_sync(0xFFFFFFFFu, dA, 1);
            float eA = ok ? __expf(dA) : 0.f;
            den += eA;
            acc0 += eA * a.y;
            acc1 += eA * a.w;
        }
    }
    acc0 += __shfl_xor_sync(0xFFFFFFFFu, acc0, 8);
    acc1 += __shfl_xor_sync(0xFFFFFFFFu, acc1, 8);
    den  += __shfl_xor_sync(0xFFFFFFFFu, den, 8);
    acc0 += __shfl_xor_sync(0xFFFFFFFFu, acc0, 16);
    acc1 += __shfl_xor_sync(0xFFFFFFFFu, acc1, 16);
    den  += __shfl_xor_sync(0xFFFFFFFFu, den, 16);
    if (quarter == 0) {
        float inv = 1.0f / fmaxf(den, 1e-16f);
        float2 sk = ((const float2*)g_skip)[w * 8 + l];
        float2 o;
        o.x = fmaxf(acc0 * inv + sk.x, 0.f);
        o.y = fmaxf(acc1 * inv + sk.y, 0.f);
        ((float2*)g_h)[w * 8 + l] = o;
    }
}

// ---------------- conv layer 2 (d=32): 16 lanes/edge, 2 edges per warp slot + fused pool ----------------
__global__ void conv2(const int* __restrict__ batch) {
    int w = (blockIdx.x * blockDim.x + threadIdx.x) >> 5;
    if (w >= NN) return;
    int lane = threadIdx.x & 31;
    int half = lane >> 4;             // which edge in the pair
    int l = lane & 15;                // element pair index (elems 2l, 2l+1)
    int row = g_row[w];
    int deg = g_deg[w];
    float2 q2 = ((const float2*)g_q)[w * 16 + l];   // pre-scaled
    const uint2* kv = (const uint2*)g_kvh;          // node n: kv[n*16 + l]
    float acc0 = 0.f, acc1 = 0.f, den = 0.f;
    for (int base = 0; base < deg; base += 32) {
        int sv = (base + lane < deg) ? g_ssrc[row + base + lane] : 0;
        int lim = min(32, deg - base);
        int j = 0;
        for (; j + 3 < lim; j += 4) {
            int sA = __shfl_sync(0xFFFFFFFFu, sv, j + half);
            int sB = __shfl_sync(0xFFFFFFFFu, sv, j + 2 + half);
            float4 a = unpack_kv(kv[sA * 16 + l]);
            float4 b = unpack_kv(kv[sB * 16 + l]);
            float dA = q2.x * a.x + q2.y * a.z;
            float dB = q2.x * b.x + q2.y * b.z;
            dA += __shfl_xor_sync(0xFFFFFFFFu, dA, 8);
            dB += __shfl_xor_sync(0xFFFFFFFFu, dB, 8);
            dA += __shfl_xor_sync(0xFFFFFFFFu, dA, 4);
            dB += __shfl_xor_sync(0xFFFFFFFFu, dB, 4);
            dA += __shfl_xor_sync(0xFFFFFFFFu, dA, 2);
            dB += __shfl_xor_sync(0xFFFFFFFFu, dB, 2);
            dA += __shfl_xor_sync(0xFFFFFFFFu, dA, 1);
            dB += __shfl_xor_sync(0xFFFFFFFFu, dB, 1);
            float eA = __expf(dA);
            float eB = __expf(dB);
            den += eA + eB;
            acc0 += eA * a.y + eB * b.y;
            acc1 += eA * a.w + eB * b.w;
        }
        for (; j < lim; j += 2) {
            bool ok = (j + half) < lim;
            int sA = __shfl_sync(0xFFFFFFFFu, sv, ok ? j + half : 0);
            float4 a = unpack_kv(kv[(ok ? sA : 0) * 16 + l]);
            float dA = q2.x * a.x + q2.y * a.z;
            dA += __shfl_xor_sync(0xFFFFFFFFu, dA, 8);
            dA += __shfl_xor_sync(0xFFFFFFFFu, dA, 4);
            dA += __shfl_xor_sync(0xFFFFFFFFu, dA, 2);
            dA += __shfl_xor_sync(0xFFFFFFFFu, dA, 1);
            float eA = ok ? __expf(dA) : 0.f;
            den += eA;
            acc0 += eA * a.y;
            acc1 += eA * a.w;
        }
    }
    acc0 += __shfl_xor_sync(0xFFFFFFFFu, acc0, 16);
    acc1 += __shfl_xor_sync(0xFFFFFFFFu, acc1, 16);
    den  += __shfl_xor_sync(0xFFFFFFFFu, den, 16);
    if (half == 0) {
        float inv = 1.0f / fmaxf(den, 1e-16f);
        float2 sk = ((const float2*)g_skip)[w * 16 + l];
        float v0 = fmaxf(acc0 * inv + sk.x, 0.f);
        float v1 = fmaxf(acc1 * inv + sk.y, 0.f);
        int g = batch[w];
        red_add2(&g_sums[g * 32 + 2 * l], v0, v1);
        if (l == 0) red_add(&g_cnt[g], 1.f);
    }
}

// ---------------- final MLP ----------------
__global__ void final_mlp(const float* __restrict__ Wf1, const float* __restrict__ bf1,
                          const float* __restrict__ Wf2, const float* __restrict__ bf2,
                          float* __restrict__ out) {
    __shared__ float sW1[32 * 64];
    __shared__ float sB1[64];
    __shared__ float sW2[64];
    __shared__ float sB2;
    for (int t = threadIdx.x; t < 32 * 64; t += blockDim.x) sW1[t] = Wf1[t];
    for (int t = threadIdx.x; t < 64; t += blockDim.x) { sB1[t] = bf1[t]; sW2[t] = Wf2[t]; }
    if (threadIdx.x == 0) sB2 = bf2[0];
    __syncthreads();
    int g = blockIdx.x * blockDim.x + threadIdx.x;
    if (g >= NG) return;
    float cnt = fmaxf(g_cnt[g], 1.f);
    float gin[32];
#pragma unroll
    for (int i = 0; i < 32; i++) gin[i] = g_sums[g * 32 + i] / cnt;
    float acc2 = sB2;
#pragma unroll
    for (int j = 0; j < 64; j++) {
        float a = sB1[j];
#pragma unroll
        for (int i = 0; i < 32; i++) a += gin[i] * sW1[i * 64 + j];
        acc2 += fmaxf(a, 0.f) * sW2[j];
    }
    out[g] = acc2;
}

// ---------------- host launch ----------------
extern "C" void kernel_launch(void* const* d_in, const int* in_sizes, int n_in,
                              void* d_out, int out_size) {
    const float* x = (const float*)d_in[0];
    const int* eidx = (const int*)d_in[1];
    const int* src = eidx;
    const int* dst = eidx + NE;
    const int* batch = (const int*)d_in[2];
    const float *Wq1 = (const float*)d_in[3], *bq1 = (const float*)d_in[4];
    const float *Wk1 = (const float*)d_in[5], *bk1 = (const float*)d_in[6];
    const float *Wv1 = (const float*)d_in[7], *bv1 = (const float*)d_in[8];
    const float *Ws1 = (const float*)d_in[9], *bs1 = (const float*)d_in[10];
    const float *Wq2 = (const float*)d_in[11], *bq2 = (const float*)d_in[12];
    const float *Wk2 = (const float*)d_in[13], *bk2 = (const float*)d_in[14];
    const float *Wv2 = (const float*)d_in[15], *bv2 = (const float*)d_in[16];
    const float *Ws2 = (const float*)d_in[17], *bs2 = (const float*)d_in[18];
    const float *Wf1 = (const float*)d_in[19], *bf1 = (const float*)d_in[20];
    const float *Wf2 = (const float*)d_in[21], *bf2 = (const float*)d_in[22];
    float* out = (float*)d_out;

    const int EB = (NE + 255) / 256;
    const int NB = (NN + 255) / 256;
    const int WB = (NN * 32 + 255) / 256;

    clear_all<<<NB, 256>>>();
    hist<<<EB, 256>>>(dst);
    scan_block<<<NBLK, 256>>>();
    scan_part<<<1, 512>>>();
    scan_add<<<NB, 256>>>();
    scatter<<<EB, 256>>>(src, dst);

    lin1<<<NB, 256>>>(x, Wq1, bq1, Wk1, bk1, Wv1, bv1, Ws1, bs1);
    conv1<<<WB, 256>>>();

    lin2<<<NB, 256>>>(Wq2, bq2, Wk2, bk2, Wv2, bv2, Ws2, bs2);
    conv2<<<WB, 256>>>(batch);

    final_mlp<<<(NG + 255) / 256, 256>>>(Wf1, bf1, Wf2, bf2, out);
}